// round 14
// baseline (speedup 1.0000x reference)
#include <cuda_runtime.h>
#include <cuda_bf16.h>
#include <math.h>
#include <stdint.h>

#define NN      100000
#define A_AT    150000
#define TROWS   750000
#define SMOOTHF 12.0f
#define MPAD_A  150016   // 2344 * 64
#define MPAD_N  100096   // 1564 * 64

// ---------------- scratch (static device globals; no allocations) ----------------
__device__ unsigned short g_xat_hi[(size_t)MPAD_A * 256];
__device__ unsigned short g_xat_lo[(size_t)MPAD_A * 256];
__device__ unsigned short g_xcl_hi[(size_t)MPAD_A * 128];
__device__ unsigned short g_xcl_lo[(size_t)MPAD_A * 128];
__device__ unsigned short g_xon_hi[(size_t)MPAD_A * 256];
__device__ unsigned short g_xon_lo[(size_t)MPAD_A * 256];
__device__ unsigned short g_hat_hi[(size_t)MPAD_A * 256];
__device__ unsigned short g_hat_lo[(size_t)MPAD_A * 256];
__device__ unsigned short g_hcl_hi[(size_t)MPAD_A * 128];
__device__ unsigned short g_hcl_lo[(size_t)MPAD_A * 128];
__device__ unsigned short g_hon_hi[(size_t)MPAD_A * 256];
__device__ unsigned short g_hon_lo[(size_t)MPAD_A * 256];
__device__ float          g_msg[(size_t)TROWS * 128];
__device__ unsigned short g_uhi[(size_t)MPAD_N * 256];
__device__ unsigned short g_ulo[(size_t)MPAD_N * 256];
__device__ unsigned short g_thi[(size_t)MPAD_N * 256];
__device__ unsigned short g_tlo[(size_t)MPAD_N * 256];
__device__ unsigned short g_whi[393216];
__device__ unsigned short g_wlo[393216];
// CSR scratch (built once per launch)
__device__ int g_deg[NN];
__device__ int g_rs[NN + 1];
__device__ int g_cur[NN];
__device__ int g_edges[TROWS];

// ---------------- helpers ----------------
__device__ __forceinline__ void cp16(void* dst, const void* src) {
    unsigned d = (unsigned)__cvta_generic_to_shared(dst);
    asm volatile("cp.async.cg.shared.global [%0], [%1], 16;" :: "r"(d), "l"(src));
}
#define CP_COMMIT() asm volatile("cp.async.commit_group;")
#define CP_WAIT(n)  asm volatile("cp.async.wait_group %0;" :: "n"(n))

__device__ __forceinline__ void mma_bf16(float* c, const unsigned* a, unsigned b0, unsigned b1) {
    asm volatile("mma.sync.aligned.m16n8k16.row.col.f32.bf16.bf16.f32 "
                 "{%0,%1,%2,%3}, {%4,%5,%6,%7}, {%8,%9}, {%0,%1,%2,%3};"
                 : "+f"(c[0]), "+f"(c[1]), "+f"(c[2]), "+f"(c[3])
                 : "r"(a[0]), "r"(a[1]), "r"(a[2]), "r"(a[3]), "r"(b0), "r"(b1));
}
__device__ __forceinline__ void ldsm4(unsigned* r, unsigned addr) {
    asm volatile("ldmatrix.sync.aligned.m8n8.x4.shared.b16 {%0,%1,%2,%3}, [%4];"
                 : "=r"(r[0]), "=r"(r[1]), "=r"(r[2]), "=r"(r[3]) : "r"(addr));
}
__device__ __forceinline__ unsigned cvt_bf16x2(float hi, float lo) {
    unsigned d; asm("cvt.rn.bf16x2.f32 %0, %1, %2;" : "=r"(d) : "f"(hi), "f"(lo)); return d;
}
__device__ __forceinline__ float bfbits(unsigned u16) { return __uint_as_float(u16 << 16); }

__device__ __forceinline__ float mish_f(float x) {
    float t = __expf(x);
    float u = fmaf(t, t, 2.f * t);
    float r = x * __fdividef(u, u + 2.f);
    return (x > 20.f) ? x : r;
}
__device__ __forceinline__ void split2(float v0, float v1, unsigned& hi, unsigned& lo) {
    unsigned u0 = __float_as_uint(v0), u1 = __float_as_uint(v1);
    hi = (u0 >> 16) | (u1 & 0xFFFF0000u);
    float l0 = v0 - __uint_as_float(u0 & 0xFFFF0000u);
    float l1 = v1 - __uint_as_float(u1 & 0xFFFF0000u);
    lo = cvt_bf16x2(l1, l0);
}

__device__ __forceinline__ int row_to_node(long long row, const int* __restrict__ at,
                                           const int* __restrict__ cl, const int* __restrict__ on)
{
    if (row < 300000) return __ldg(at + row);
    if (row < 450000) return __ldg(cl + row - 300000);
    return __ldg(on + row - 450000);
}

// ---------------- fused weight transpose/split (ONE launch) ----------------
__global__ void convW_all(const float* __restrict__ w0, const float* __restrict__ w1,
                          const float* __restrict__ w2, const float* __restrict__ w3,
                          const float* __restrict__ w4, const float* __restrict__ w5,
                          const float* __restrict__ w6, const float* __restrict__ w7,
                          unsigned short* __restrict__ hi, unsigned short* __restrict__ lo)
{
    int i = blockIdx.x * blockDim.x + threadIdx.x;
    if (i >= 393216) return;
    const float* W; int base, K, N;
    if      (i < 131072) { if (i < 65536)  { W = w0; base = 0;      } else { W = w1; base = 65536;  } K = 256; N = 256; }
    else if (i < 163840) { if (i < 147456) { W = w2; base = 131072; } else { W = w3; base = 147456; } K = 128; N = 128; }
    else if (i < 294912) { if (i < 229376) { W = w4; base = 163840; } else { W = w5; base = 229376; } K = 256; N = 256; }
    else if (i < 360448) { W = w6; base = 294912; K = 256; N = 256; }
    else                 { W = w7; base = 360448; K = 256; N = 128; }
    int li = i - base;
    int k = li / N, n = li - k * N;
    float x = W[li];
    unsigned u = __float_as_uint(x);
    float r = x - __uint_as_float(u & 0xFFFF0000u);
    __nv_bfloat16 lb = __float2bfloat16_rn(r);
    hi[(size_t)base + (size_t)n * K + k] = (unsigned short)(u >> 16);
    lo[(size_t)base + (size_t)n * K + k] = *(unsigned short*)&lb;
}

// ---------------- CSR build (once per launch) ----------------
__global__ void count_deg(const int* __restrict__ at, const int* __restrict__ cl,
                          const int* __restrict__ on, int* __restrict__ deg)
{
    int i = blockIdx.x * blockDim.x + threadIdx.x;
    if (i >= TROWS) return;
    atomicAdd(deg + row_to_node(i, at, cl, on), 1);
}

__global__ void scan_deg(const int* __restrict__ deg, int* __restrict__ rs)
{
    __shared__ int buf[1024];
    __shared__ int carry;
    int t = threadIdx.x;
    if (t == 0) carry = 0;
    __syncthreads();
    for (int base = 0; base < NN; base += 1024) {
        int v = (base + t < NN) ? deg[base + t] : 0;
        buf[t] = v;
        __syncthreads();
        for (int off = 1; off < 1024; off <<= 1) {
            int x = (t >= off) ? buf[t - off] : 0;
            __syncthreads();
            buf[t] += x;
            __syncthreads();
        }
        if (base + t < NN) rs[base + t + 1] = carry + buf[t];
        __syncthreads();
        if (t == 1023) carry += buf[1023];
        __syncthreads();
    }
    if (t == 0) rs[0] = 0;
}

__global__ void scatter_edges(const int* __restrict__ at, const int* __restrict__ cl,
                              const int* __restrict__ on, const int* __restrict__ rs,
                              int* __restrict__ cur, int* __restrict__ edges)
{
    int i = blockIdx.x * blockDim.x + threadIdx.x;
    if (i >= TROWS) return;
    int n = row_to_node(i, at, cl, on);
    int pos = __ldg(rs + n) + atomicAdd(cur + n, 1);
    edges[pos] = i;
}

// ---------------- batched HMMA GEMM, CTA 64x128, 3 CTAs/SM (proven shape) ----------------
struct BatchArgs {
    const unsigned short* Ahi[3]; const unsigned short* Alo[3];
    const unsigned short* Bhi[3]; const unsigned short* Blo[3];
    const float*          bias[3];
    const unsigned short* Xhi[3]; const unsigned short* Xlo[3];
    const float*          Xf[3];
    unsigned short*       Chi[3]; unsigned short* Clo[3];
    float*                Cf[3];
    int N[3]; int K[3];
};

#define KC 32
#define STAGE_BYTES 30720
#define OFF_AH 0
#define OFF_AL 5120
#define OFF_BH 10240
#define OFF_BL 20480

#define PICK(f) ((z == 0) ? a.f[0] : (z == 1) ? a.f[1] : a.f[2])

template<int MODE>
__global__ void __launch_bounds__(256, 3) gemm_hmma(BatchArgs a, int M)
{
    extern __shared__ char sm[];
    const unsigned sbase = (unsigned)__cvta_generic_to_shared(sm);
    const int z    = blockIdx.z;
    const int N    = PICK(N);
    const int K    = PICK(K);
    const int col0 = blockIdx.x * 128;
    if (col0 >= N) return;
    const unsigned short* Ahi = PICK(Ahi);
    const unsigned short* Alo = PICK(Alo);
    const unsigned short* Bhi = PICK(Bhi);
    const unsigned short* Blo = PICK(Blo);

    const int tid  = threadIdx.x;
    const int wid  = tid >> 5, lane = tid & 31;
    const int g    = lane >> 2, t = lane & 3;
    const int wm   = wid & 1,  wn = wid >> 1;       // 2 x 4 warp grid, warp tile 32x32
    const int row0 = blockIdx.y * 64;
    const int nc   = K >> 5;

    float c[2][4][4];
#pragma unroll
    for (int i = 0; i < 2; i++)
#pragma unroll
        for (int j = 0; j < 4; j++)
#pragma unroll
            for (int q = 0; q < 4; q++) c[i][j][q] = 0.f;

    auto issue = [&](int ch) {
        char* sb = sm + (ch & 1) * STAGE_BYTES;
#pragma unroll
        for (int rep = 0; rep < 2; rep++) {
            int id  = tid + rep * 256;
            int row = id >> 2, q = id & 3;
            size_t gB = (size_t)(col0 + row) * K + ch * KC + q * 8;
            int so = row * 80 + q * 16;
            cp16(sb + OFF_BH + so, Bhi + gB);
            cp16(sb + OFF_BL + so, Blo + gB);
        }
        {
            int row = tid >> 2, q = tid & 3;
            size_t gA = (size_t)(row0 + row) * K + ch * KC + q * 8;
            int so = row * 80 + q * 16;
            cp16(sb + OFF_AH + so, Ahi + gA);
            cp16(sb + OFF_AL + so, Alo + gA);
        }
    };

    issue(0); CP_COMMIT();

    const int aRowLane = (lane & 7) + ((lane >> 3) & 1) * 8;
    const int aKb      = (lane >> 4) * 16;
    const int bRowLane = (lane & 7) + ((lane >> 4) & 1) * 8;
    const int bKb      = ((lane >> 3) & 1) * 16;

#pragma unroll 1
    for (int ch = 0; ch < nc; ch++) {
        CP_WAIT(0);
        __syncthreads();
        if (ch + 1 < nc) { issue(ch + 1); CP_COMMIT(); }
        const unsigned sb = sbase + (ch & 1) * STAGE_BYTES;
#pragma unroll
        for (int ks = 0; ks < 2; ks++) {
            unsigned ah[2][4], al[2][4], bh[2][4], bl[2][4];
#pragma unroll
            for (int mt = 0; mt < 2; mt++) {
                unsigned aoff = (unsigned)(wm * 32 + mt * 16 + aRowLane) * 80 + ks * 32 + aKb;
                ldsm4(ah[mt], sb + OFF_AH + aoff);
                ldsm4(al[mt], sb + OFF_AL + aoff);
            }
#pragma unroll
            for (int p = 0; p < 2; p++) {
                unsigned boff = (unsigned)(wn * 32 + p * 16 + bRowLane) * 80 + ks * 32 + bKb;
                ldsm4(bh[p], sb + OFF_BH + boff);
                ldsm4(bl[p], sb + OFF_BL + boff);
            }
#pragma unroll
            for (int p = 0; p < 2; p++)
#pragma unroll
                for (int mt = 0; mt < 2; mt++) {
                    mma_bf16(c[mt][2 * p],     ah[mt], bh[p][0], bh[p][1]);
                    mma_bf16(c[mt][2 * p + 1], ah[mt], bh[p][2], bh[p][3]);
                }
#pragma unroll
            for (int p = 0; p < 2; p++)
#pragma unroll
                for (int mt = 0; mt < 2; mt++) {
                    mma_bf16(c[mt][2 * p],     al[mt], bh[p][0], bh[p][1]);
                    mma_bf16(c[mt][2 * p + 1], al[mt], bh[p][2], bh[p][3]);
                }
#pragma unroll
            for (int p = 0; p < 2; p++)
#pragma unroll
                for (int mt = 0; mt < 2; mt++) {
                    mma_bf16(c[mt][2 * p],     ah[mt], bl[p][0], bl[p][1]);
                    mma_bf16(c[mt][2 * p + 1], ah[mt], bl[p][2], bl[p][3]);
                }
        }
    }
    __syncthreads();

    // ---- epilogue ----
    const float* bias = PICK(bias);
#pragma unroll
    for (int mt = 0; mt < 2; mt++)
#pragma unroll
    for (int half = 0; half < 2; half++) {
        int r = row0 + wm * 32 + mt * 16 + g + half * 8;
        if (r < M) {
#pragma unroll
            for (int nt = 0; nt < 4; nt++) {
                int col = col0 + wn * 32 + nt * 8 + t * 2;
                float v0 = c[mt][nt][half * 2 + 0] + __ldg(bias + col);
                float v1 = c[mt][nt][half * 2 + 1] + __ldg(bias + col + 1);
                size_t idxo = (size_t)r * N + col;
                if (MODE == 0) {
                    v0 = mish_f(v0); v1 = mish_f(v1);
                    unsigned hi, lo;
                    split2(v0, v1, hi, lo);
                    *(unsigned*)(PICK(Chi) + idxo) = hi;
                    *(unsigned*)(PICK(Clo) + idxo) = lo;
                } else if (MODE == 1) {
                    unsigned xh = *(const unsigned*)(PICK(Xhi) + idxo);
                    unsigned xl = *(const unsigned*)(PICK(Xlo) + idxo);
                    v0 += bfbits(xh & 0xFFFFu) + bfbits(xl & 0xFFFFu);
                    v1 += bfbits(xh >> 16)     + bfbits(xl >> 16);
                    float2 o; o.x = v0; o.y = v1;
                    *(float2*)(PICK(Cf) + idxo) = o;
                } else {
                    float2 x = *(const float2*)(PICK(Xf) + idxo);
                    float2 o; o.x = v0 + x.x; o.y = v1 + x.y;
                    *(float2*)(PICK(Cf) + idxo) = o;
                }
            }
        }
    }
}

// ---------------- batched gather ----------------
__global__ void gather_all(const float* __restrict__ h,
                           const int* __restrict__ at, const int* __restrict__ cl,
                           const int* __restrict__ on,
                           unsigned short* __restrict__ xat_hi, unsigned short* __restrict__ xat_lo,
                           unsigned short* __restrict__ xcl_hi, unsigned short* __restrict__ xcl_lo,
                           unsigned short* __restrict__ xon_hi, unsigned short* __restrict__ xon_lo)
{
    long long i = (long long)blockIdx.x * blockDim.x + threadIdx.x;
    if (i >= (long long)TROWS * 32) return;
    long long seg = i >> 5;
    int f4 = (int)(i & 31) * 4;
    int node;
    unsigned short *dhi, *dlo;
    size_t off;
    if (seg < 300000) {
        node = __ldg(at + seg); off = (size_t)seg * 128 + f4; dhi = xat_hi; dlo = xat_lo;
    } else if (seg < 450000) {
        long long s = seg - 300000;
        node = __ldg(cl + s); off = (size_t)s * 128 + f4; dhi = xcl_hi; dlo = xcl_lo;
    } else {
        long long s = seg - 450000;
        node = __ldg(on + s); off = (size_t)s * 128 + f4; dhi = xon_hi; dlo = xon_lo;
    }
    float4 v = *(const float4*)(h + (size_t)node * 128 + f4);
    unsigned h01, l01, h23, l23;
    split2(v.x, v.y, h01, l01);
    split2(v.z, v.w, h23, l23);
    *(uint2*)(dhi + off) = make_uint2(h01, h23);
    *(uint2*)(dlo + off) = make_uint2(l01, l23);
}

// ---------------- CSR aggregation: SINGLE-PASS online logsumexp, zero atomics ----------------
// warp per node; lane l owns elements 4l..4l+3
__global__ void __launch_bounds__(256) aggregate_updin(
    const float* __restrict__ msg,
    const int* __restrict__ rs, const int* __restrict__ edges,
    const float* __restrict__ h,
    unsigned short* __restrict__ uhi, unsigned short* __restrict__ ulo)
{
    int w = threadIdx.x >> 5, l = threadIdx.x & 31;
    int node = blockIdx.x * 8 + w;
    if (node >= NN) return;
    int s0 = __ldg(rs + node), s1 = __ldg(rs + node + 1);

    float4 m = make_float4(-3.4e38f, -3.4e38f, -3.4e38f, -3.4e38f);
    float4 s = make_float4(0.f, 0.f, 0.f, 0.f);
    int e_next = (s0 < s1) ? __ldg(edges + s0) : 0;
    for (int i = s0; i < s1; i++) {
        int e = e_next;
        if (i + 1 < s1) e_next = __ldg(edges + i + 1);
        float4 v = *(const float4*)(msg + (size_t)e * 128 + 4 * l);
        // online logsumexp per component: one exp per element
        {
            float d = SMOOTHF * (v.x - m.x);
            if (d > 0.f) { s.x = s.x * __expf(-d) + 1.f; m.x = v.x; } else s.x += __expf(d);
        }
        {
            float d = SMOOTHF * (v.y - m.y);
            if (d > 0.f) { s.y = s.y * __expf(-d) + 1.f; m.y = v.y; } else s.y += __expf(d);
        }
        {
            float d = SMOOTHF * (v.z - m.z);
            if (d > 0.f) { s.z = s.z * __expf(-d) + 1.f; m.z = v.z; } else s.z += __expf(d);
        }
        {
            float d = SMOOTHF * (v.w - m.w);
            if (d > 0.f) { s.w = s.w * __expf(-d) + 1.f; m.w = v.w; } else s.w += __expf(d);
        }
    }
    if (s1 == s0) {       // empty segment: reference clamps seg_max to 0, sum = 0
        m = make_float4(0.f, 0.f, 0.f, 0.f);
        s = make_float4(0.f, 0.f, 0.f, 0.f);
    }
    const float inv = 1.0f / SMOOTHF;
    float4 mm;
    mm.x = logf(s.x + 1e-16f) * inv + m.x;
    mm.y = logf(s.y + 1e-16f) * inv + m.y;
    mm.z = logf(s.z + 1e-16f) * inv + m.z;
    mm.w = logf(s.w + 1e-16f) * inv + m.w;

    size_t ub = (size_t)node * 256 + 4 * l;
    unsigned h01, l01, h23, l23;
    split2(mm.x, mm.y, h01, l01);
    split2(mm.z, mm.w, h23, l23);
    *(uint2*)(uhi + ub) = make_uint2(h01, h23);
    *(uint2*)(ulo + ub) = make_uint2(l01, l23);

    float4 hv = *(const float4*)(h + (size_t)node * 128 + 4 * l);
    split2(hv.x, hv.y, h01, l01);
    split2(hv.z, hv.w, h23, l23);
    *(uint2*)(uhi + ub + 128) = make_uint2(h01, h23);
    *(uint2*)(ulo + ub + 128) = make_uint2(l01, l23);
}

// ---------------- host launch ----------------
extern "C" void kernel_launch(void* const* d_in, const int* in_sizes, int n_in,
                              void* d_out, int out_size)
{
    const float *emb, *w_in[3], *b_in[3], *w_out[3], *b_out[3], *wui, *bui, *wuo, *buo;
    const int *at, *cl, *on;

    if (in_sizes[2] == 65536) {
        emb = (const float*)d_in[0];
        at  = (const int*)d_in[1];
        w_in[0] = (const float*)d_in[2];  b_in[0] = (const float*)d_in[3];
        w_out[0] = (const float*)d_in[4]; b_out[0] = (const float*)d_in[5];
        cl  = (const int*)d_in[6];
        w_in[1] = (const float*)d_in[7];  b_in[1] = (const float*)d_in[8];
        w_out[1] = (const float*)d_in[9]; b_out[1] = (const float*)d_in[10];
        on  = (const int*)d_in[11];
        w_in[2] = (const float*)d_in[12];  b_in[2] = (const float*)d_in[13];
        w_out[2] = (const float*)d_in[14]; b_out[2] = (const float*)d_in[15];
        wui = (const float*)d_in[16]; bui = (const float*)d_in[17];
        wuo = (const float*)d_in[18]; buo = (const float*)d_in[19];
    } else {
        emb = (const float*)d_in[0];
        at  = (const int*)d_in[1];
        cl  = (const int*)d_in[2];
        on  = (const int*)d_in[3];
        w_in[0] = (const float*)d_in[4];  b_in[0] = (const float*)d_in[5];
        w_out[0] = (const float*)d_in[6]; b_out[0] = (const float*)d_in[7];
        w_in[1] = (const float*)d_in[8];  b_in[1] = (const float*)d_in[9];
        w_out[1] = (const float*)d_in[10]; b_out[1] = (const float*)d_in[11];
        w_in[2] = (const float*)d_in[12];  b_in[2] = (const float*)d_in[13];
        w_out[2] = (const float*)d_in[14]; b_out[2] = (const float*)d_in[15];
        wui = (const float*)d_in[16]; bui = (const float*)d_in[17];
        wuo = (const float*)d_in[18]; buo = (const float*)d_in[19];
    }

    float* h = (float*)d_out;
    unsigned short *xat_hi, *xat_lo, *xcl_hi, *xcl_lo, *xon_hi, *xon_lo;
    unsigned short *hat_hi, *hat_lo, *hcl_hi, *hcl_lo, *hon_hi, *hon_lo;
    unsigned short *uhi, *ulo, *thi, *tlo, *whi, *wlo;
    float *msg;
    int *deg, *rs, *cur, *edges;
    cudaGetSymbolAddress((void**)&xat_hi, g_xat_hi); cudaGetSymbolAddress((void**)&xat_lo, g_xat_lo);
    cudaGetSymbolAddress((void**)&xcl_hi, g_xcl_hi); cudaGetSymbolAddress((void**)&xcl_lo, g_xcl_lo);
    cudaGetSymbolAddress((void**)&xon_hi, g_xon_hi); cudaGetSymbolAddress((void**)&xon_lo, g_xon_lo);
    cudaGetSymbolAddress((void**)&hat_hi, g_hat_hi); cudaGetSymbolAddress((void**)&hat_lo, g_hat_lo);
    cudaGetSymbolAddress((void**)&hcl_hi, g_hcl_hi); cudaGetSymbolAddress((void**)&hcl_lo, g_hcl_lo);
    cudaGetSymbolAddress((void**)&hon_hi, g_hon_hi); cudaGetSymbolAddress((void**)&hon_lo, g_hon_lo);
    cudaGetSymbolAddress((void**)&uhi, g_uhi);  cudaGetSymbolAddress((void**)&ulo, g_ulo);
    cudaGetSymbolAddress((void**)&thi, g_thi);  cudaGetSymbolAddress((void**)&tlo, g_tlo);
    cudaGetSymbolAddress((void**)&whi, g_whi);  cudaGetSymbolAddress((void**)&wlo, g_wlo);
    cudaGetSymbolAddress((void**)&msg, g_msg);
    cudaGetSymbolAddress((void**)&deg, g_deg);
    cudaGetSymbolAddress((void**)&rs, g_rs);
    cudaGetSymbolAddress((void**)&cur, g_cur);
    cudaGetSymbolAddress((void**)&edges, g_edges);

    const size_t O_AT_IN = 0, O_AT_OUT = 65536, O_CL_IN = 131072, O_CL_OUT = 147456,
                 O_ON_IN = 163840, O_ON_OUT = 229376, O_U_IN = 294912, O_U_OUT = 360448;

    convW_all<<<(393216 + 255) / 256, 256>>>(w_in[0], w_out[0], w_in[1], w_out[1],
                                             w_in[2], w_out[2], wui, wuo, whi, wlo);

    // ---- CSR build (once) ----
    cudaMemsetAsync(deg, 0, NN * sizeof(int));
    cudaMemsetAsync(cur, 0, NN * sizeof(int));
    count_deg<<<(TROWS + 255) / 256, 256>>>(at, cl, on, deg);
    scan_deg<<<1, 1024>>>(deg, rs);
    scatter_edges<<<(TROWS + 255) / 256, 256>>>(at, cl, on, rs, cur, edges);

    const int SMEM = 2 * STAGE_BYTES;   // 61440
    cudaFuncSetAttribute(gemm_hmma<0>, cudaFuncAttributeMaxDynamicSharedMemorySize, SMEM);
    cudaFuncSetAttribute(gemm_hmma<1>, cudaFuncAttributeMaxDynamicSharedMemorySize, SMEM);
    cudaFuncSetAttribute(gemm_hmma<2>, cudaFuncAttributeMaxDynamicSharedMemorySize, SMEM);

    cudaMemcpyAsync(h, emb, (size_t)NN * 128 * sizeof(float), cudaMemcpyDeviceToDevice);

    // ---- batch argument blocks ----
    BatchArgs gin = {};   // relation in-GEMMs (MODE 0)
    BatchArgs gout = {};  // relation out-GEMMs (MODE 1)
    BatchArgs gu0 = {};   // update hidden GEMM (MODE 0)
    BatchArgs gu1 = {};   // update out GEMM (MODE 2)

    const unsigned short* xh[3] = { xat_hi, xcl_hi, xon_hi };
    const unsigned short* xl[3] = { xat_lo, xcl_lo, xon_lo };
    unsigned short* hh_[3] = { hat_hi, hcl_hi, hon_hi };
    unsigned short* hl_[3] = { hat_lo, hcl_lo, hon_lo };
    const size_t wIn[3]  = { O_AT_IN, O_CL_IN, O_ON_IN };
    const size_t wOut[3] = { O_AT_OUT, O_CL_OUT, O_ON_OUT };
    const int nz[3] = { 256, 128, 256 };
    const size_t msgOff[3] = { 0, (size_t)300000 * 128, (size_t)450000 * 128 };

    for (int zz = 0; zz < 3; zz++) {
        gin.Ahi[zz] = xh[zz];  gin.Alo[zz] = xl[zz];
        gin.Bhi[zz] = whi + wIn[zz]; gin.Blo[zz] = wlo + wIn[zz];
        gin.bias[zz] = b_in[zz];
        gin.Chi[zz] = hh_[zz]; gin.Clo[zz] = hl_[zz];
        gin.N[zz] = nz[zz]; gin.K[zz] = nz[zz];

        gout.Ahi[zz] = hh_[zz]; gout.Alo[zz] = hl_[zz];
        gout.Bhi[zz] = whi + wOut[zz]; gout.Blo[zz] = wlo + wOut[zz];
        gout.bias[zz] = b_out[zz];
        gout.Xhi[zz] = xh[zz]; gout.Xlo[zz] = xl[zz];
        gout.Cf[zz] = msg + msgOff[zz];
        gout.N[zz] = nz[zz]; gout.K[zz] = nz[zz];
    }
    gu0.Ahi[0] = uhi; gu0.Alo[0] = ulo;
    gu0.Bhi[0] = whi + O_U_IN; gu0.Blo[0] = wlo + O_U_IN;
    gu0.bias[0] = bui; gu0.Chi[0] = thi; gu0.Clo[0] = tlo;
    gu0.N[0] = 256; gu0.K[0] = 256;

    gu1.Ahi[0] = thi; gu1.Alo[0] = tlo;
    gu1.Bhi[0] = whi + O_U_OUT; gu1.Blo[0] = wlo + O_U_OUT;
    gu1.bias[0] = buo; gu1.Xf[0] = h; gu1.Cf[0] = h;
    gu1.N[0] = 128; gu1.K[0] = 256;

    const dim3 gRel(2, MPAD_A / 64, 3);
    const dim3 gUp0(2, MPAD_N / 64, 1);
    const dim3 gUp1(1, MPAD_N / 64, 1);

    for (int layer = 0; layer < 4; layer++) {
        gather_all<<<(int)(((long long)TROWS * 32 + 255) / 256), 256>>>(
            h, at, cl, on, xat_hi, xat_lo, xcl_hi, xcl_lo, xon_hi, xon_lo);

        gemm_hmma<0><<<gRel, 256, SMEM>>>(gin, A_AT);
        gemm_hmma<1><<<gRel, 256, SMEM>>>(gout, A_AT);

        aggregate_updin<<<(NN + 7) / 8, 256>>>(msg, rs, edges, h, uhi, ulo);

        gemm_hmma<0><<<gUp0, 256, SMEM>>>(gu0, NN);
        gemm_hmma<2><<<gUp1, 256, SMEM>>>(gu1, NN);
    }
}

// round 15
// speedup vs baseline: 1.0221x; 1.0221x over previous
#include <cuda_runtime.h>
#include <cuda_bf16.h>
#include <math.h>
#include <stdint.h>

#define NN      100000
#define A_AT    150000
#define TROWS   750000
#define SMOOTHF 12.0f
#define MPAD_A  150016   // 2344 * 64
#define MPAD_N  100096   // 1564 * 64

// ---------------- scratch (static device globals; no allocations) ----------------
__device__ unsigned short g_xat_hi[(size_t)MPAD_A * 256];
__device__ unsigned short g_xat_lo[(size_t)MPAD_A * 256];
__device__ unsigned short g_xcl_hi[(size_t)MPAD_A * 128];
__device__ unsigned short g_xcl_lo[(size_t)MPAD_A * 128];
__device__ unsigned short g_xon_hi[(size_t)MPAD_A * 256];
__device__ unsigned short g_xon_lo[(size_t)MPAD_A * 256];
__device__ unsigned short g_hat_hi[(size_t)MPAD_A * 256];
__device__ unsigned short g_hat_lo[(size_t)MPAD_A * 256];
__device__ unsigned short g_hcl_hi[(size_t)MPAD_A * 128];
__device__ unsigned short g_hcl_lo[(size_t)MPAD_A * 128];
__device__ unsigned short g_hon_hi[(size_t)MPAD_A * 256];
__device__ unsigned short g_hon_lo[(size_t)MPAD_A * 256];
__device__ float          g_msg[(size_t)TROWS * 128];
__device__ unsigned short g_uhi[(size_t)MPAD_N * 256];
__device__ unsigned short g_ulo[(size_t)MPAD_N * 256];
__device__ unsigned short g_thi[(size_t)MPAD_N * 256];
__device__ unsigned short g_tlo[(size_t)MPAD_N * 256];
__device__ unsigned short g_whi[393216];
__device__ unsigned short g_wlo[393216];
// CSR scratch (built once per launch)
__device__ int g_deg[NN];
__device__ int g_rs[NN + 1];
__device__ int g_cur[NN];
__device__ int g_edges[TROWS];

// ---------------- helpers ----------------
__device__ __forceinline__ void cp16(void* dst, const void* src) {
    unsigned d = (unsigned)__cvta_generic_to_shared(dst);
    asm volatile("cp.async.cg.shared.global [%0], [%1], 16;" :: "r"(d), "l"(src));
}
#define CP_COMMIT() asm volatile("cp.async.commit_group;")
#define CP_WAIT(n)  asm volatile("cp.async.wait_group %0;" :: "n"(n))

__device__ __forceinline__ void mma_bf16(float* c, const unsigned* a, unsigned b0, unsigned b1) {
    asm volatile("mma.sync.aligned.m16n8k16.row.col.f32.bf16.bf16.f32 "
                 "{%0,%1,%2,%3}, {%4,%5,%6,%7}, {%8,%9}, {%0,%1,%2,%3};"
                 : "+f"(c[0]), "+f"(c[1]), "+f"(c[2]), "+f"(c[3])
                 : "r"(a[0]), "r"(a[1]), "r"(a[2]), "r"(a[3]), "r"(b0), "r"(b1));
}
__device__ __forceinline__ void ldsm4(unsigned* r, unsigned addr) {
    asm volatile("ldmatrix.sync.aligned.m8n8.x4.shared.b16 {%0,%1,%2,%3}, [%4];"
                 : "=r"(r[0]), "=r"(r[1]), "=r"(r[2]), "=r"(r[3]) : "r"(addr));
}
__device__ __forceinline__ unsigned cvt_bf16x2(float hi, float lo) {
    unsigned d; asm("cvt.rn.bf16x2.f32 %0, %1, %2;" : "=r"(d) : "f"(hi), "f"(lo)); return d;
}
__device__ __forceinline__ float bfbits(unsigned u16) { return __uint_as_float(u16 << 16); }

__device__ __forceinline__ float mish_f(float x) {
    float t = __expf(x);
    float u = fmaf(t, t, 2.f * t);
    float r = x * __fdividef(u, u + 2.f);
    return (x > 20.f) ? x : r;
}
__device__ __forceinline__ void split2(float v0, float v1, unsigned& hi, unsigned& lo) {
    unsigned u0 = __float_as_uint(v0), u1 = __float_as_uint(v1);
    hi = (u0 >> 16) | (u1 & 0xFFFF0000u);
    float l0 = v0 - __uint_as_float(u0 & 0xFFFF0000u);
    float l1 = v1 - __uint_as_float(u1 & 0xFFFF0000u);
    lo = cvt_bf16x2(l1, l0);
}

__device__ __forceinline__ int row_to_node(long long row, const int* __restrict__ at,
                                           const int* __restrict__ cl, const int* __restrict__ on)
{
    if (row < 300000) return __ldg(at + row);
    if (row < 450000) return __ldg(cl + row - 300000);
    return __ldg(on + row - 450000);
}

// ---------------- fused weight transpose/split (ONE launch) ----------------
__global__ void convW_all(const float* __restrict__ w0, const float* __restrict__ w1,
                          const float* __restrict__ w2, const float* __restrict__ w3,
                          const float* __restrict__ w4, const float* __restrict__ w5,
                          const float* __restrict__ w6, const float* __restrict__ w7,
                          unsigned short* __restrict__ hi, unsigned short* __restrict__ lo)
{
    int i = blockIdx.x * blockDim.x + threadIdx.x;
    if (i >= 393216) return;
    const float* W; int base, K, N;
    if      (i < 131072) { if (i < 65536)  { W = w0; base = 0;      } else { W = w1; base = 65536;  } K = 256; N = 256; }
    else if (i < 163840) { if (i < 147456) { W = w2; base = 131072; } else { W = w3; base = 147456; } K = 128; N = 128; }
    else if (i < 294912) { if (i < 229376) { W = w4; base = 163840; } else { W = w5; base = 229376; } K = 256; N = 256; }
    else if (i < 360448) { W = w6; base = 294912; K = 256; N = 256; }
    else                 { W = w7; base = 360448; K = 256; N = 128; }
    int li = i - base;
    int k = li / N, n = li - k * N;
    float x = W[li];
    unsigned u = __float_as_uint(x);
    float r = x - __uint_as_float(u & 0xFFFF0000u);
    __nv_bfloat16 lb = __float2bfloat16_rn(r);
    hi[(size_t)base + (size_t)n * K + k] = (unsigned short)(u >> 16);
    lo[(size_t)base + (size_t)n * K + k] = *(unsigned short*)&lb;
}

// ---------------- CSR build (once per launch) ----------------
__global__ void count_deg(const int* __restrict__ at, const int* __restrict__ cl,
                          const int* __restrict__ on, int* __restrict__ deg)
{
    int i = blockIdx.x * blockDim.x + threadIdx.x;
    if (i >= TROWS) return;
    atomicAdd(deg + row_to_node(i, at, cl, on), 1);
}

// warp-shuffle scan: 1024 threads, 3 syncs per 1024-chunk
__global__ void scan_deg(const int* __restrict__ deg, int* __restrict__ rs)
{
    __shared__ int wsum[32];
    __shared__ int carry;
    int t = threadIdx.x;
    int lane = t & 31, warp = t >> 5;
    if (t == 0) carry = 0;
    __syncthreads();
    for (int base = 0; base < NN; base += 1024) {
        int v = (base + t < NN) ? deg[base + t] : 0;
        int x = v;
#pragma unroll
        for (int off = 1; off < 32; off <<= 1) {
            int y = __shfl_up_sync(0xFFFFFFFFu, x, off);
            if (lane >= off) x += y;
        }
        if (lane == 31) wsum[warp] = x;
        __syncthreads();
        if (warp == 0) {
            int w = wsum[lane];
#pragma unroll
            for (int off = 1; off < 32; off <<= 1) {
                int y = __shfl_up_sync(0xFFFFFFFFu, w, off);
                if (lane >= off) w += y;
            }
            wsum[lane] = w;
        }
        __syncthreads();
        int total = wsum[31];
        int pre = (warp > 0) ? wsum[warp - 1] : 0;
        if (base + t < NN) rs[base + t + 1] = carry + pre + x;
        __syncthreads();
        if (t == 0) carry += total;
        __syncthreads();
    }
    if (threadIdx.x == 0) rs[0] = 0;
}

__global__ void scatter_edges(const int* __restrict__ at, const int* __restrict__ cl,
                              const int* __restrict__ on, const int* __restrict__ rs,
                              int* __restrict__ cur, int* __restrict__ edges)
{
    int i = blockIdx.x * blockDim.x + threadIdx.x;
    if (i >= TROWS) return;
    int n = row_to_node(i, at, cl, on);
    int pos = __ldg(rs + n) + atomicAdd(cur + n, 1);
    edges[pos] = i;
}

// ---------------- batched HMMA GEMM, CTA 64x128, 3 CTAs/SM (proven shape) ----------------
struct BatchArgs {
    const unsigned short* Ahi[3]; const unsigned short* Alo[3];
    const unsigned short* Bhi[3]; const unsigned short* Blo[3];
    const float*          bias[3];
    const unsigned short* Xhi[3]; const unsigned short* Xlo[3];
    const float*          Xf[3];
    unsigned short*       Chi[3]; unsigned short* Clo[3];
    float*                Cf[3];
    int N[3]; int K[3];
};

#define KC 32
#define STAGE_BYTES 30720
#define OFF_AH 0
#define OFF_AL 5120
#define OFF_BH 10240
#define OFF_BL 20480

#define PICK(f) ((z == 0) ? a.f[0] : (z == 1) ? a.f[1] : a.f[2])

template<int MODE>
__global__ void __launch_bounds__(256, 3) gemm_hmma(BatchArgs a, int M)
{
    extern __shared__ char sm[];
    const unsigned sbase = (unsigned)__cvta_generic_to_shared(sm);
    const int z    = blockIdx.z;
    const int N    = PICK(N);
    const int K    = PICK(K);
    const int col0 = blockIdx.x * 128;
    if (col0 >= N) return;
    const unsigned short* Ahi = PICK(Ahi);
    const unsigned short* Alo = PICK(Alo);
    const unsigned short* Bhi = PICK(Bhi);
    const unsigned short* Blo = PICK(Blo);

    const int tid  = threadIdx.x;
    const int wid  = tid >> 5, lane = tid & 31;
    const int g    = lane >> 2, t = lane & 3;
    const int wm   = wid & 1,  wn = wid >> 1;       // 2 x 4 warp grid, warp tile 32x32
    const int row0 = blockIdx.y * 64;
    const int nc   = K >> 5;

    float c[2][4][4];
#pragma unroll
    for (int i = 0; i < 2; i++)
#pragma unroll
        for (int j = 0; j < 4; j++)
#pragma unroll
            for (int q = 0; q < 4; q++) c[i][j][q] = 0.f;

    auto issue = [&](int ch) {
        char* sb = sm + (ch & 1) * STAGE_BYTES;
#pragma unroll
        for (int rep = 0; rep < 2; rep++) {
            int id  = tid + rep * 256;
            int row = id >> 2, q = id & 3;
            size_t gB = (size_t)(col0 + row) * K + ch * KC + q * 8;
            int so = row * 80 + q * 16;
            cp16(sb + OFF_BH + so, Bhi + gB);
            cp16(sb + OFF_BL + so, Blo + gB);
        }
        {
            int row = tid >> 2, q = tid & 3;
            size_t gA = (size_t)(row0 + row) * K + ch * KC + q * 8;
            int so = row * 80 + q * 16;
            cp16(sb + OFF_AH + so, Ahi + gA);
            cp16(sb + OFF_AL + so, Alo + gA);
        }
    };

    issue(0); CP_COMMIT();

    const int aRowLane = (lane & 7) + ((lane >> 3) & 1) * 8;
    const int aKb      = (lane >> 4) * 16;
    const int bRowLane = (lane & 7) + ((lane >> 4) & 1) * 8;
    const int bKb      = ((lane >> 3) & 1) * 16;

#pragma unroll 1
    for (int ch = 0; ch < nc; ch++) {
        CP_WAIT(0);
        __syncthreads();
        if (ch + 1 < nc) { issue(ch + 1); CP_COMMIT(); }
        const unsigned sb = sbase + (ch & 1) * STAGE_BYTES;
#pragma unroll
        for (int ks = 0; ks < 2; ks++) {
            unsigned ah[2][4], al[2][4], bh[2][4], bl[2][4];
#pragma unroll
            for (int mt = 0; mt < 2; mt++) {
                unsigned aoff = (unsigned)(wm * 32 + mt * 16 + aRowLane) * 80 + ks * 32 + aKb;
                ldsm4(ah[mt], sb + OFF_AH + aoff);
                ldsm4(al[mt], sb + OFF_AL + aoff);
            }
#pragma unroll
            for (int p = 0; p < 2; p++) {
                unsigned boff = (unsigned)(wn * 32 + p * 16 + bRowLane) * 80 + ks * 32 + bKb;
                ldsm4(bh[p], sb + OFF_BH + boff);
                ldsm4(bl[p], sb + OFF_BL + boff);
            }
#pragma unroll
            for (int p = 0; p < 2; p++)
#pragma unroll
                for (int mt = 0; mt < 2; mt++) {
                    mma_bf16(c[mt][2 * p],     ah[mt], bh[p][0], bh[p][1]);
                    mma_bf16(c[mt][2 * p + 1], ah[mt], bh[p][2], bh[p][3]);
                }
#pragma unroll
            for (int p = 0; p < 2; p++)
#pragma unroll
                for (int mt = 0; mt < 2; mt++) {
                    mma_bf16(c[mt][2 * p],     al[mt], bh[p][0], bh[p][1]);
                    mma_bf16(c[mt][2 * p + 1], al[mt], bh[p][2], bh[p][3]);
                }
#pragma unroll
            for (int p = 0; p < 2; p++)
#pragma unroll
                for (int mt = 0; mt < 2; mt++) {
                    mma_bf16(c[mt][2 * p],     ah[mt], bl[p][0], bl[p][1]);
                    mma_bf16(c[mt][2 * p + 1], ah[mt], bl[p][2], bl[p][3]);
                }
        }
    }
    __syncthreads();

    // ---- epilogue ----
    const float* bias = PICK(bias);
#pragma unroll
    for (int mt = 0; mt < 2; mt++)
#pragma unroll
    for (int half = 0; half < 2; half++) {
        int r = row0 + wm * 32 + mt * 16 + g + half * 8;
        if (r < M) {
#pragma unroll
            for (int nt = 0; nt < 4; nt++) {
                int col = col0 + wn * 32 + nt * 8 + t * 2;
                float v0 = c[mt][nt][half * 2 + 0] + __ldg(bias + col);
                float v1 = c[mt][nt][half * 2 + 1] + __ldg(bias + col + 1);
                size_t idxo = (size_t)r * N + col;
                if (MODE == 0) {
                    v0 = mish_f(v0); v1 = mish_f(v1);
                    unsigned hi, lo;
                    split2(v0, v1, hi, lo);
                    *(unsigned*)(PICK(Chi) + idxo) = hi;
                    *(unsigned*)(PICK(Clo) + idxo) = lo;
                } else if (MODE == 1) {
                    unsigned xh = *(const unsigned*)(PICK(Xhi) + idxo);
                    unsigned xl = *(const unsigned*)(PICK(Xlo) + idxo);
                    v0 += bfbits(xh & 0xFFFFu) + bfbits(xl & 0xFFFFu);
                    v1 += bfbits(xh >> 16)     + bfbits(xl >> 16);
                    float2 o; o.x = v0; o.y = v1;
                    *(float2*)(PICK(Cf) + idxo) = o;
                } else {
                    float2 x = *(const float2*)(PICK(Xf) + idxo);
                    float2 o; o.x = v0 + x.x; o.y = v1 + x.y;
                    *(float2*)(PICK(Cf) + idxo) = o;
                }
            }
        }
    }
}

// ---------------- batched gather ----------------
__global__ void gather_all(const float* __restrict__ h,
                           const int* __restrict__ at, const int* __restrict__ cl,
                           const int* __restrict__ on,
                           unsigned short* __restrict__ xat_hi, unsigned short* __restrict__ xat_lo,
                           unsigned short* __restrict__ xcl_hi, unsigned short* __restrict__ xcl_lo,
                           unsigned short* __restrict__ xon_hi, unsigned short* __restrict__ xon_lo)
{
    long long i = (long long)blockIdx.x * blockDim.x + threadIdx.x;
    if (i >= (long long)TROWS * 32) return;
    long long seg = i >> 5;
    int f4 = (int)(i & 31) * 4;
    int node;
    unsigned short *dhi, *dlo;
    size_t off;
    if (seg < 300000) {
        node = __ldg(at + seg); off = (size_t)seg * 128 + f4; dhi = xat_hi; dlo = xat_lo;
    } else if (seg < 450000) {
        long long s = seg - 300000;
        node = __ldg(cl + s); off = (size_t)s * 128 + f4; dhi = xcl_hi; dlo = xcl_lo;
    } else {
        long long s = seg - 450000;
        node = __ldg(on + s); off = (size_t)s * 128 + f4; dhi = xon_hi; dlo = xon_lo;
    }
    float4 v = *(const float4*)(h + (size_t)node * 128 + f4);
    unsigned h01, l01, h23, l23;
    split2(v.x, v.y, h01, l01);
    split2(v.z, v.w, h23, l23);
    *(uint2*)(dhi + off) = make_uint2(h01, h23);
    *(uint2*)(dlo + off) = make_uint2(l01, l23);
}

// ---------------- CSR aggregation: two-pass max/expsum (R13 form), zero atomics ----------------
// warp per node; lane l owns elements 4l..4l+3
__global__ void aggregate_updin(const float* __restrict__ msg,
                                const int* __restrict__ rs, const int* __restrict__ edges,
                                const float* __restrict__ h,
                                unsigned short* __restrict__ uhi, unsigned short* __restrict__ ulo)
{
    int w = threadIdx.x >> 5, l = threadIdx.x & 31;
    int node = blockIdx.x * 4 + w;
    if (node >= NN) return;
    int s0 = __ldg(rs + node), s1 = __ldg(rs + node + 1);

    float4 m = make_float4(0.f, 0.f, 0.f, 0.f);
    if (s1 > s0) {
        m = make_float4(-3.4e38f, -3.4e38f, -3.4e38f, -3.4e38f);
        for (int i = s0; i < s1; i++) {
            int e = __ldg(edges + i);
            float4 v = *(const float4*)(msg + (size_t)e * 128 + 4 * l);
            m.x = fmaxf(m.x, v.x); m.y = fmaxf(m.y, v.y);
            m.z = fmaxf(m.z, v.z); m.w = fmaxf(m.w, v.w);
        }
    }
    float4 s = make_float4(0.f, 0.f, 0.f, 0.f);
    for (int i = s0; i < s1; i++) {
        int e = __ldg(edges + i);
        float4 v = *(const float4*)(msg + (size_t)e * 128 + 4 * l);
        s.x += __expf(SMOOTHF * (v.x - m.x));
        s.y += __expf(SMOOTHF * (v.y - m.y));
        s.z += __expf(SMOOTHF * (v.z - m.z));
        s.w += __expf(SMOOTHF * (v.w - m.w));
    }
    const float inv = 1.0f / SMOOTHF;
    float4 mm;
    mm.x = logf(s.x + 1e-16f) * inv + m.x;
    mm.y = logf(s.y + 1e-16f) * inv + m.y;
    mm.z = logf(s.z + 1e-16f) * inv + m.z;
    mm.w = logf(s.w + 1e-16f) * inv + m.w;

    size_t ub = (size_t)node * 256 + 4 * l;
    unsigned h01, l01, h23, l23;
    split2(mm.x, mm.y, h01, l01);
    split2(mm.z, mm.w, h23, l23);
    *(uint2*)(uhi + ub) = make_uint2(h01, h23);
    *(uint2*)(ulo + ub) = make_uint2(l01, l23);

    float4 hv = *(const float4*)(h + (size_t)node * 128 + 4 * l);
    split2(hv.x, hv.y, h01, l01);
    split2(hv.z, hv.w, h23, l23);
    *(uint2*)(uhi + ub + 128) = make_uint2(h01, h23);
    *(uint2*)(ulo + ub + 128) = make_uint2(l01, l23);
}

// ---------------- host launch ----------------
extern "C" void kernel_launch(void* const* d_in, const int* in_sizes, int n_in,
                              void* d_out, int out_size)
{
    const float *emb, *w_in[3], *b_in[3], *w_out[3], *b_out[3], *wui, *bui, *wuo, *buo;
    const int *at, *cl, *on;

    if (in_sizes[2] == 65536) {
        emb = (const float*)d_in[0];
        at  = (const int*)d_in[1];
        w_in[0] = (const float*)d_in[2];  b_in[0] = (const float*)d_in[3];
        w_out[0] = (const float*)d_in[4]; b_out[0] = (const float*)d_in[5];
        cl  = (const int*)d_in[6];
        w_in[1] = (const float*)d_in[7];  b_in[1] = (const float*)d_in[8];
        w_out[1] = (const float*)d_in[9]; b_out[1] = (const float*)d_in[10];
        on  = (const int*)d_in[11];
        w_in[2] = (const float*)d_in[12];  b_in[2] = (const float*)d_in[13];
        w_out[2] = (const float*)d_in[14]; b_out[2] = (const float*)d_in[15];
        wui = (const float*)d_in[16]; bui = (const float*)d_in[17];
        wuo = (const float*)d_in[18]; buo = (const float*)d_in[19];
    } else {
        emb = (const float*)d_in[0];
        at  = (const int*)d_in[1];
        cl  = (const int*)d_in[2];
        on  = (const int*)d_in[3];
        w_in[0] = (const float*)d_in[4];  b_in[0] = (const float*)d_in[5];
        w_out[0] = (const float*)d_in[6]; b_out[0] = (const float*)d_in[7];
        w_in[1] = (const float*)d_in[8];  b_in[1] = (const float*)d_in[9];
        w_out[1] = (const float*)d_in[10]; b_out[1] = (const float*)d_in[11];
        w_in[2] = (const float*)d_in[12];  b_in[2] = (const float*)d_in[13];
        w_out[2] = (const float*)d_in[14]; b_out[2] = (const float*)d_in[15];
        wui = (const float*)d_in[16]; bui = (const float*)d_in[17];
        wuo = (const float*)d_in[18]; buo = (const float*)d_in[19];
    }

    float* h = (float*)d_out;
    unsigned short *xat_hi, *xat_lo, *xcl_hi, *xcl_lo, *xon_hi, *xon_lo;
    unsigned short *hat_hi, *hat_lo, *hcl_hi, *hcl_lo, *hon_hi, *hon_lo;
    unsigned short *uhi, *ulo, *thi, *tlo, *whi, *wlo;
    float *msg;
    int *deg, *rs, *cur, *edges;
    cudaGetSymbolAddress((void**)&xat_hi, g_xat_hi); cudaGetSymbolAddress((void**)&xat_lo, g_xat_lo);
    cudaGetSymbolAddress((void**)&xcl_hi, g_xcl_hi); cudaGetSymbolAddress((void**)&xcl_lo, g_xcl_lo);
    cudaGetSymbolAddress((void**)&xon_hi, g_xon_hi); cudaGetSymbolAddress((void**)&xon_lo, g_xon_lo);
    cudaGetSymbolAddress((void**)&hat_hi, g_hat_hi); cudaGetSymbolAddress((void**)&hat_lo, g_hat_lo);
    cudaGetSymbolAddress((void**)&hcl_hi, g_hcl_hi); cudaGetSymbolAddress((void**)&hcl_lo, g_hcl_lo);
    cudaGetSymbolAddress((void**)&hon_hi, g_hon_hi); cudaGetSymbolAddress((void**)&hon_lo, g_hon_lo);
    cudaGetSymbolAddress((void**)&uhi, g_uhi);  cudaGetSymbolAddress((void**)&ulo, g_ulo);
    cudaGetSymbolAddress((void**)&thi, g_thi);  cudaGetSymbolAddress((void**)&tlo, g_tlo);
    cudaGetSymbolAddress((void**)&whi, g_whi);  cudaGetSymbolAddress((void**)&wlo, g_wlo);
    cudaGetSymbolAddress((void**)&msg, g_msg);
    cudaGetSymbolAddress((void**)&deg, g_deg);
    cudaGetSymbolAddress((void**)&rs, g_rs);
    cudaGetSymbolAddress((void**)&cur, g_cur);
    cudaGetSymbolAddress((void**)&edges, g_edges);

    const size_t O_AT_IN = 0, O_AT_OUT = 65536, O_CL_IN = 131072, O_CL_OUT = 147456,
                 O_ON_IN = 163840, O_ON_OUT = 229376, O_U_IN = 294912, O_U_OUT = 360448;

    convW_all<<<(393216 + 255) / 256, 256>>>(w_in[0], w_out[0], w_in[1], w_out[1],
                                             w_in[2], w_out[2], wui, wuo, whi, wlo);

    // ---- CSR build (once) ----
    cudaMemsetAsync(deg, 0, NN * sizeof(int));
    cudaMemsetAsync(cur, 0, NN * sizeof(int));
    count_deg<<<(TROWS + 255) / 256, 256>>>(at, cl, on, deg);
    scan_deg<<<1, 1024>>>(deg, rs);
    scatter_edges<<<(TROWS + 255) / 256, 256>>>(at, cl, on, rs, cur, edges);

    const int SMEM = 2 * STAGE_BYTES;   // 61440
    cudaFuncSetAttribute(gemm_hmma<0>, cudaFuncAttributeMaxDynamicSharedMemorySize, SMEM);
    cudaFuncSetAttribute(gemm_hmma<1>, cudaFuncAttributeMaxDynamicSharedMemorySize, SMEM);
    cudaFuncSetAttribute(gemm_hmma<2>, cudaFuncAttributeMaxDynamicSharedMemorySize, SMEM);

    cudaMemcpyAsync(h, emb, (size_t)NN * 128 * sizeof(float), cudaMemcpyDeviceToDevice);

    // ---- batch argument blocks ----
    BatchArgs gin = {};   // relation in-GEMMs (MODE 0)
    BatchArgs gout = {};  // relation out-GEMMs (MODE 1)
    BatchArgs gu0 = {};   // update hidden GEMM (MODE 0)
    BatchArgs gu1 = {};   // update out GEMM (MODE 2)

    const unsigned short* xh[3] = { xat_hi, xcl_hi, xon_hi };
    const unsigned short* xl[3] = { xat_lo, xcl_lo, xon_lo };
    unsigned short* hh_[3] = { hat_hi, hcl_hi, hon_hi };
    unsigned short* hl_[3] = { hat_lo, hcl_lo, hon_lo };
    const size_t wIn[3]  = { O_AT_IN, O_CL_IN, O_ON_IN };
    const size_t wOut[3] = { O_AT_OUT, O_CL_OUT, O_ON_OUT };
    const int nz[3] = { 256, 128, 256 };
    const size_t msgOff[3] = { 0, (size_t)300000 * 128, (size_t)450000 * 128 };

    for (int zz = 0; zz < 3; zz++) {
        gin.Ahi[zz] = xh[zz];  gin.Alo[zz] = xl[zz];
        gin.Bhi[zz] = whi + wIn[zz]; gin.Blo[zz] = wlo + wIn[zz];
        gin.bias[zz] = b_in[zz];
        gin.Chi[zz] = hh_[zz]; gin.Clo[zz] = hl_[zz];
        gin.N[zz] = nz[zz]; gin.K[zz] = nz[zz];

        gout.Ahi[zz] = hh_[zz]; gout.Alo[zz] = hl_[zz];
        gout.Bhi[zz] = whi + wOut[zz]; gout.Blo[zz] = wlo + wOut[zz];
        gout.bias[zz] = b_out[zz];
        gout.Xhi[zz] = xh[zz]; gout.Xlo[zz] = xl[zz];
        gout.Cf[zz] = msg + msgOff[zz];
        gout.N[zz] = nz[zz]; gout.K[zz] = nz[zz];
    }
    gu0.Ahi[0] = uhi; gu0.Alo[0] = ulo;
    gu0.Bhi[0] = whi + O_U_IN; gu0.Blo[0] = wlo + O_U_IN;
    gu0.bias[0] = bui; gu0.Chi[0] = thi; gu0.Clo[0] = tlo;
    gu0.N[0] = 256; gu0.K[0] = 256;

    gu1.Ahi[0] = thi; gu1.Alo[0] = tlo;
    gu1.Bhi[0] = whi + O_U_OUT; gu1.Blo[0] = wlo + O_U_OUT;
    gu1.bias[0] = buo; gu1.Xf[0] = h; gu1.Cf[0] = h;
    gu1.N[0] = 128; gu1.K[0] = 256;

    const dim3 gRel(2, MPAD_A / 64, 3);
    const dim3 gUp0(2, MPAD_N / 64, 1);
    const dim3 gUp1(1, MPAD_N / 64, 1);

    for (int layer = 0; layer < 4; layer++) {
        gather_all<<<(int)(((long long)TROWS * 32 + 255) / 256), 256>>>(
            h, at, cl, on, xat_hi, xat_lo, xcl_hi, xcl_lo, xon_hi, xon_lo);

        gemm_hmma<0><<<gRel, 256, SMEM>>>(gin, A_AT);
        gemm_hmma<1><<<gRel, 256, SMEM>>>(gout, A_AT);

        aggregate_updin<<<(NN + 3) / 4, 128>>>(msg, rs, edges, h, uhi, ulo);

        gemm_hmma<0><<<gUp0, 256, SMEM>>>(gu0, NN);
        gemm_hmma<2><<<gUp1, 256, SMEM>>>(gu1, NN);
    }
}

// round 16
// speedup vs baseline: 1.0891x; 1.0655x over previous
#include <cuda_runtime.h>
#include <cuda_bf16.h>
#include <math.h>
#include <stdint.h>

#define NN      100000
#define A_AT    150000
#define TROWS   750000
#define SMOOTHF 12.0f
#define MPAD_A  150016   // 2344 * 64
#define MPAD_N  100096   // 1564 * 64

// ---------------- scratch (static device globals; no allocations) ----------------
__device__ unsigned short g_hat_hi[(size_t)MPAD_A * 256];
__device__ unsigned short g_hat_lo[(size_t)MPAD_A * 256];
__device__ unsigned short g_hcl_hi[(size_t)MPAD_A * 128];
__device__ unsigned short g_hcl_lo[(size_t)MPAD_A * 128];
__device__ unsigned short g_hon_hi[(size_t)MPAD_A * 256];
__device__ unsigned short g_hon_lo[(size_t)MPAD_A * 256];
__device__ float          g_msg[(size_t)TROWS * 128];
__device__ unsigned short g_uhi[(size_t)MPAD_N * 256];
__device__ unsigned short g_ulo[(size_t)MPAD_N * 256];
__device__ unsigned short g_thi[(size_t)MPAD_N * 256];
__device__ unsigned short g_tlo[(size_t)MPAD_N * 256];
__device__ unsigned short g_whi[393216];
__device__ unsigned short g_wlo[393216];
// CSR scratch (built once per launch)
__device__ int g_deg[NN];
__device__ int g_rs[NN + 1];
__device__ int g_cur[NN];
__device__ int g_edges[TROWS];

// ---------------- helpers ----------------
__device__ __forceinline__ void cp16(void* dst, const void* src) {
    unsigned d = (unsigned)__cvta_generic_to_shared(dst);
    asm volatile("cp.async.cg.shared.global [%0], [%1], 16;" :: "r"(d), "l"(src));
}
#define CP_COMMIT() asm volatile("cp.async.commit_group;")
#define CP_WAIT(n)  asm volatile("cp.async.wait_group %0;" :: "n"(n))

__device__ __forceinline__ void mma_bf16(float* c, const unsigned* a, unsigned b0, unsigned b1) {
    asm volatile("mma.sync.aligned.m16n8k16.row.col.f32.bf16.bf16.f32 "
                 "{%0,%1,%2,%3}, {%4,%5,%6,%7}, {%8,%9}, {%0,%1,%2,%3};"
                 : "+f"(c[0]), "+f"(c[1]), "+f"(c[2]), "+f"(c[3])
                 : "r"(a[0]), "r"(a[1]), "r"(a[2]), "r"(a[3]), "r"(b0), "r"(b1));
}
__device__ __forceinline__ void ldsm4(unsigned* r, unsigned addr) {
    asm volatile("ldmatrix.sync.aligned.m8n8.x4.shared.b16 {%0,%1,%2,%3}, [%4];"
                 : "=r"(r[0]), "=r"(r[1]), "=r"(r[2]), "=r"(r[3]) : "r"(addr));
}
__device__ __forceinline__ float2 lds2(unsigned addr) {
    float2 r;
    asm volatile("ld.shared.v2.f32 {%0,%1}, [%2];" : "=f"(r.x), "=f"(r.y) : "r"(addr));
    return r;
}
__device__ __forceinline__ unsigned cvt_bf16x2(float hi, float lo) {
    unsigned d; asm("cvt.rn.bf16x2.f32 %0, %1, %2;" : "=r"(d) : "f"(hi), "f"(lo)); return d;
}

__device__ __forceinline__ float mish_f(float x) {
    float t = __expf(x);
    float u = fmaf(t, t, 2.f * t);
    float r = x * __fdividef(u, u + 2.f);
    return (x > 20.f) ? x : r;
}
__device__ __forceinline__ void split2(float v0, float v1, unsigned& hi, unsigned& lo) {
    unsigned u0 = __float_as_uint(v0), u1 = __float_as_uint(v1);
    hi = (u0 >> 16) | (u1 & 0xFFFF0000u);
    float l0 = v0 - __uint_as_float(u0 & 0xFFFF0000u);
    float l1 = v1 - __uint_as_float(u1 & 0xFFFF0000u);
    lo = cvt_bf16x2(l1, l0);
}

__device__ __forceinline__ int row_to_node(long long row, const int* __restrict__ at,
                                           const int* __restrict__ cl, const int* __restrict__ on)
{
    if (row < 300000) return __ldg(at + row);
    if (row < 450000) return __ldg(cl + row - 300000);
    return __ldg(on + row - 450000);
}

// ---------------- fused weight transpose/split (ONE launch) ----------------
__global__ void convW_all(const float* __restrict__ w0, const float* __restrict__ w1,
                          const float* __restrict__ w2, const float* __restrict__ w3,
                          const float* __restrict__ w4, const float* __restrict__ w5,
                          const float* __restrict__ w6, const float* __restrict__ w7,
                          unsigned short* __restrict__ hi, unsigned short* __restrict__ lo)
{
    int i = blockIdx.x * blockDim.x + threadIdx.x;
    if (i >= 393216) return;
    const float* W; int base, K, N;
    if      (i < 131072) { if (i < 65536)  { W = w0; base = 0;      } else { W = w1; base = 65536;  } K = 256; N = 256; }
    else if (i < 163840) { if (i < 147456) { W = w2; base = 131072; } else { W = w3; base = 147456; } K = 128; N = 128; }
    else if (i < 294912) { if (i < 229376) { W = w4; base = 163840; } else { W = w5; base = 229376; } K = 256; N = 256; }
    else if (i < 360448) { W = w6; base = 294912; K = 256; N = 256; }
    else                 { W = w7; base = 360448; K = 256; N = 128; }
    int li = i - base;
    int k = li / N, n = li - k * N;
    float x = W[li];
    unsigned u = __float_as_uint(x);
    float r = x - __uint_as_float(u & 0xFFFF0000u);
    __nv_bfloat16 lb = __float2bfloat16_rn(r);
    hi[(size_t)base + (size_t)n * K + k] = (unsigned short)(u >> 16);
    lo[(size_t)base + (size_t)n * K + k] = *(unsigned short*)&lb;
}

// ---------------- CSR build (once per launch) ----------------
__global__ void count_deg(const int* __restrict__ at, const int* __restrict__ cl,
                          const int* __restrict__ on, int* __restrict__ deg)
{
    int i = blockIdx.x * blockDim.x + threadIdx.x;
    if (i >= TROWS) return;
    atomicAdd(deg + row_to_node(i, at, cl, on), 1);
}

__global__ void scan_deg(const int* __restrict__ deg, int* __restrict__ rs)
{
    __shared__ int wsum[32];
    __shared__ int carry;
    int t = threadIdx.x;
    int lane = t & 31, warp = t >> 5;
    if (t == 0) carry = 0;
    __syncthreads();
    for (int base = 0; base < NN; base += 1024) {
        int v = (base + t < NN) ? deg[base + t] : 0;
        int x = v;
#pragma unroll
        for (int off = 1; off < 32; off <<= 1) {
            int y = __shfl_up_sync(0xFFFFFFFFu, x, off);
            if (lane >= off) x += y;
        }
        if (lane == 31) wsum[warp] = x;
        __syncthreads();
        if (warp == 0) {
            int w = wsum[lane];
#pragma unroll
            for (int off = 1; off < 32; off <<= 1) {
                int y = __shfl_up_sync(0xFFFFFFFFu, w, off);
                if (lane >= off) w += y;
            }
            wsum[lane] = w;
        }
        __syncthreads();
        int total = wsum[31];
        int pre = (warp > 0) ? wsum[warp - 1] : 0;
        if (base + t < NN) rs[base + t + 1] = carry + pre + x;
        __syncthreads();
        if (t == 0) carry += total;
        __syncthreads();
    }
    if (threadIdx.x == 0) rs[0] = 0;
}

__global__ void scatter_edges(const int* __restrict__ at, const int* __restrict__ cl,
                              const int* __restrict__ on, const int* __restrict__ rs,
                              int* __restrict__ cur, int* __restrict__ edges)
{
    int i = blockIdx.x * blockDim.x + threadIdx.x;
    if (i >= TROWS) return;
    int n = row_to_node(i, at, cl, on);
    int pos = __ldg(rs + n) + atomicAdd(cur + n, 1);
    edges[pos] = i;
}

// ---------------- batched HMMA GEMM, CTA 64x128, 3 CTAs/SM ----------------
// GA=true: A gathered as f32 from hsrc via idx, fragments assembled manually (hi+lo from one load)
struct BatchArgs {
    const unsigned short* Ahi[3]; const unsigned short* Alo[3];
    const unsigned short* Bhi[3]; const unsigned short* Blo[3];
    const float*          bias[3];
    const float*          Xf[3];
    unsigned short*       Chi[3]; unsigned short* Clo[3];
    float*                Cf[3];
    const int*            idx[3];
    int N[3]; int K[3];
};

#define KC 32
#define STAGE_BYTES 30720
#define PITCH_AF 144
#define OFF_AH 0
#define OFF_AL 5120
#define OFF_BH 10240
#define OFF_BL 20480

#define PICK(f) ((z == 0) ? a.f[0] : (z == 1) ? a.f[1] : a.f[2])

template<int MODE, bool GA>
__global__ void __launch_bounds__(256, 3) gemm_hmma(BatchArgs a, const float* __restrict__ hsrc, int M)
{
    extern __shared__ char sm[];
    const unsigned sbase = (unsigned)__cvta_generic_to_shared(sm);
    const int z    = blockIdx.z;
    const int N    = PICK(N);
    const int K    = PICK(K);
    const int col0 = blockIdx.x * 128;
    if (col0 >= N) return;
    const unsigned short* Ahi = PICK(Ahi);
    const unsigned short* Alo = PICK(Alo);
    const unsigned short* Bhi = PICK(Bhi);
    const unsigned short* Blo = PICK(Blo);
    const int* gidx = PICK(idx);

    const int tid  = threadIdx.x;
    const int wid  = tid >> 5, lane = tid & 31;
    const int g    = lane >> 2, t = lane & 3;
    const int wm   = wid & 1,  wn = wid >> 1;       // 2 x 4 warp grid, warp tile 32x32
    const int row0 = blockIdx.y * 64;
    const int nc   = K >> 5;

    float c[2][4][4];
#pragma unroll
    for (int i = 0; i < 2; i++)
#pragma unroll
        for (int j = 0; j < 4; j++)
#pragma unroll
            for (int q = 0; q < 4; q++) c[i][j][q] = 0.f;

    auto issue = [&](int ch) {
        char* sb = sm + (ch & 1) * STAGE_BYTES;
#pragma unroll
        for (int rep = 0; rep < 2; rep++) {
            int id  = tid + rep * 256;
            int row = id >> 2, q = id & 3;
            size_t gB = (size_t)(col0 + row) * K + ch * KC + q * 8;
            int so = row * 80 + q * 16;
            cp16(sb + OFF_BH + so, Bhi + gB);
            cp16(sb + OFF_BL + so, Blo + gB);
        }
        if (GA) {
            int row = tid >> 2, q = tid & 3;
            int gr = row0 + row;
            int node = (gr < M) ? __ldg(gidx + (K >> 7) * gr + ((ch * KC) >> 7)) : 0;
            const float* src = hsrc + (size_t)node * 128 + ((ch * KC) & 127) + q * 8;
            int so = row * PITCH_AF + q * 32;
            cp16(sb + so, src);
            cp16(sb + so + 16, src + 4);
        } else {
            int row = tid >> 2, q = tid & 3;
            size_t gA = (size_t)(row0 + row) * K + ch * KC + q * 8;
            int so = row * 80 + q * 16;
            cp16(sb + OFF_AH + so, Ahi + gA);
            cp16(sb + OFF_AL + so, Alo + gA);
        }
    };

    issue(0); CP_COMMIT();

    const int aRowLane = (lane & 7) + ((lane >> 3) & 1) * 8;
    const int aKb      = (lane >> 4) * 16;
    const int bRowLane = (lane & 7) + ((lane >> 4) & 1) * 8;
    const int bKb      = ((lane >> 3) & 1) * 16;

#pragma unroll 1
    for (int ch = 0; ch < nc; ch++) {
        CP_WAIT(0);
        __syncthreads();
        if (ch + 1 < nc) { issue(ch + 1); CP_COMMIT(); }
        const unsigned sb = sbase + (ch & 1) * STAGE_BYTES;
#pragma unroll
        for (int ks = 0; ks < 2; ks++) {
            unsigned ah[2][4], al[2][4], bh[2][4], bl[2][4];
            if (GA) {
#pragma unroll
                for (int mt = 0; mt < 2; mt++) {
                    unsigned rb = sb + (unsigned)(wm * 32 + mt * 16 + g) * PITCH_AF
                                + ks * 64 + t * 8;
                    float2 p0 = lds2(rb);
                    float2 p1 = lds2(rb + 8 * PITCH_AF);
                    float2 p2 = lds2(rb + 32);
                    float2 p3 = lds2(rb + 8 * PITCH_AF + 32);
                    split2(p0.x, p0.y, ah[mt][0], al[mt][0]);
                    split2(p1.x, p1.y, ah[mt][1], al[mt][1]);
                    split2(p2.x, p2.y, ah[mt][2], al[mt][2]);
                    split2(p3.x, p3.y, ah[mt][3], al[mt][3]);
                }
            } else {
#pragma unroll
                for (int mt = 0; mt < 2; mt++) {
                    unsigned aoff = (unsigned)(wm * 32 + mt * 16 + aRowLane) * 80 + ks * 32 + aKb;
                    ldsm4(ah[mt], sb + OFF_AH + aoff);
                    ldsm4(al[mt], sb + OFF_AL + aoff);
                }
            }
#pragma unroll
            for (int p = 0; p < 2; p++) {
                unsigned boff = (unsigned)(wn * 32 + p * 16 + bRowLane) * 80 + ks * 32 + bKb;
                ldsm4(bh[p], sb + OFF_BH + boff);
                ldsm4(bl[p], sb + OFF_BL + boff);
            }
#pragma unroll
            for (int p = 0; p < 2; p++)
#pragma unroll
                for (int mt = 0; mt < 2; mt++) {
                    mma_bf16(c[mt][2 * p],     ah[mt], bh[p][0], bh[p][1]);
                    mma_bf16(c[mt][2 * p + 1], ah[mt], bh[p][2], bh[p][3]);
                }
#pragma unroll
            for (int p = 0; p < 2; p++)
#pragma unroll
                for (int mt = 0; mt < 2; mt++) {
                    mma_bf16(c[mt][2 * p],     al[mt], bh[p][0], bh[p][1]);
                    mma_bf16(c[mt][2 * p + 1], al[mt], bh[p][2], bh[p][3]);
                }
#pragma unroll
            for (int p = 0; p < 2; p++)
#pragma unroll
                for (int mt = 0; mt < 2; mt++) {
                    mma_bf16(c[mt][2 * p],     ah[mt], bl[p][0], bl[p][1]);
                    mma_bf16(c[mt][2 * p + 1], ah[mt], bl[p][2], bl[p][3]);
                }
        }
    }
    __syncthreads();

    // ---- epilogue ----
    const float* bias = PICK(bias);
#pragma unroll
    for (int mt = 0; mt < 2; mt++)
#pragma unroll
    for (int half = 0; half < 2; half++) {
        int r = row0 + wm * 32 + mt * 16 + g + half * 8;
        if (r < M) {
#pragma unroll
            for (int nt = 0; nt < 4; nt++) {
                int col = col0 + wn * 32 + nt * 8 + t * 2;
                float v0 = c[mt][nt][half * 2 + 0] + __ldg(bias + col);
                float v1 = c[mt][nt][half * 2 + 1] + __ldg(bias + col + 1);
                size_t idxo = (size_t)r * N + col;
                if (MODE == 0) {
                    v0 = mish_f(v0); v1 = mish_f(v1);
                    unsigned hi, lo;
                    split2(v0, v1, hi, lo);
                    *(unsigned*)(PICK(Chi) + idxo) = hi;
                    *(unsigned*)(PICK(Clo) + idxo) = lo;
                } else if (MODE == 1) {
                    // residual = gathered h (exact f32)
                    int node = __ldg(gidx + (N >> 7) * r + (col >> 7));
                    float2 x = *(const float2*)(hsrc + (size_t)node * 128 + (col & 127));
                    float2 o; o.x = v0 + x.x; o.y = v1 + x.y;
                    *(float2*)(PICK(Cf) + idxo) = o;
                } else {
                    float2 x = *(const float2*)(PICK(Xf) + idxo);
                    float2 o; o.x = v0 + x.x; o.y = v1 + x.y;
                    *(float2*)(PICK(Cf) + idxo) = o;
                }
            }
        }
    }
}

// ---------------- CSR aggregation: two-pass max/expsum, zero atomics ----------------
__global__ void aggregate_updin(const float* __restrict__ msg,
                                const int* __restrict__ rs, const int* __restrict__ edges,
                                const float* __restrict__ h,
                                unsigned short* __restrict__ uhi, unsigned short* __restrict__ ulo)
{
    int w = threadIdx.x >> 5, l = threadIdx.x & 31;
    int node = blockIdx.x * 4 + w;
    if (node >= NN) return;
    int s0 = __ldg(rs + node), s1 = __ldg(rs + node + 1);

    float4 m = make_float4(0.f, 0.f, 0.f, 0.f);
    if (s1 > s0) {
        m = make_float4(-3.4e38f, -3.4e38f, -3.4e38f, -3.4e38f);
        for (int i = s0; i < s1; i++) {
            int e = __ldg(edges + i);
            float4 v = *(const float4*)(msg + (size_t)e * 128 + 4 * l);
            m.x = fmaxf(m.x, v.x); m.y = fmaxf(m.y, v.y);
            m.z = fmaxf(m.z, v.z); m.w = fmaxf(m.w, v.w);
        }
    }
    float4 s = make_float4(0.f, 0.f, 0.f, 0.f);
    for (int i = s0; i < s1; i++) {
        int e = __ldg(edges + i);
        float4 v = *(const float4*)(msg + (size_t)e * 128 + 4 * l);
        s.x += __expf(SMOOTHF * (v.x - m.x));
        s.y += __expf(SMOOTHF * (v.y - m.y));
        s.z += __expf(SMOOTHF * (v.z - m.z));
        s.w += __expf(SMOOTHF * (v.w - m.w));
    }
    const float inv = 1.0f / SMOOTHF;
    float4 mm;
    mm.x = logf(s.x + 1e-16f) * inv + m.x;
    mm.y = logf(s.y + 1e-16f) * inv + m.y;
    mm.z = logf(s.z + 1e-16f) * inv + m.z;
    mm.w = logf(s.w + 1e-16f) * inv + m.w;

    size_t ub = (size_t)node * 256 + 4 * l;
    unsigned h01, l01, h23, l23;
    split2(mm.x, mm.y, h01, l01);
    split2(mm.z, mm.w, h23, l23);
    *(uint2*)(uhi + ub) = make_uint2(h01, h23);
    *(uint2*)(ulo + ub) = make_uint2(l01, l23);

    float4 hv = *(const float4*)(h + (size_t)node * 128 + 4 * l);
    split2(hv.x, hv.y, h01, l01);
    split2(hv.z, hv.w, h23, l23);
    *(uint2*)(uhi + ub + 128) = make_uint2(h01, h23);
    *(uint2*)(ulo + ub + 128) = make_uint2(l01, l23);
}

// ---------------- host launch ----------------
extern "C" void kernel_launch(void* const* d_in, const int* in_sizes, int n_in,
                              void* d_out, int out_size)
{
    const float *emb, *w_in[3], *b_in[3], *w_out[3], *b_out[3], *wui, *bui, *wuo, *buo;
    const int *at, *cl, *on;

    if (in_sizes[2] == 65536) {
        emb = (const float*)d_in[0];
        at  = (const int*)d_in[1];
        w_in[0] = (const float*)d_in[2];  b_in[0] = (const float*)d_in[3];
        w_out[0] = (const float*)d_in[4]; b_out[0] = (const float*)d_in[5];
        cl  = (const int*)d_in[6];
        w_in[1] = (const float*)d_in[7];  b_in[1] = (const float*)d_in[8];
        w_out[1] = (const float*)d_in[9]; b_out[1] = (const float*)d_in[10];
        on  = (const int*)d_in[11];
        w_in[2] = (const float*)d_in[12];  b_in[2] = (const float*)d_in[13];
        w_out[2] = (const float*)d_in[14]; b_out[2] = (const float*)d_in[15];
        wui = (const float*)d_in[16]; bui = (const float*)d_in[17];
        wuo = (const float*)d_in[18]; buo = (const float*)d_in[19];
    } else {
        emb = (const float*)d_in[0];
        at  = (const int*)d_in[1];
        cl  = (const int*)d_in[2];
        on  = (const int*)d_in[3];
        w_in[0] = (const float*)d_in[4];  b_in[0] = (const float*)d_in[5];
        w_out[0] = (const float*)d_in[6]; b_out[0] = (const float*)d_in[7];
        w_in[1] = (const float*)d_in[8];  b_in[1] = (const float*)d_in[9];
        w_out[1] = (const float*)d_in[10]; b_out[1] = (const float*)d_in[11];
        w_in[2] = (const float*)d_in[12];  b_in[2] = (const float*)d_in[13];
        w_out[2] = (const float*)d_in[14]; b_out[2] = (const float*)d_in[15];
        wui = (const float*)d_in[16]; bui = (const float*)d_in[17];
        wuo = (const float*)d_in[18]; buo = (const float*)d_in[19];
    }

    float* h = (float*)d_out;
    unsigned short *hat_hi, *hat_lo, *hcl_hi, *hcl_lo, *hon_hi, *hon_lo;
    unsigned short *uhi, *ulo, *thi, *tlo, *whi, *wlo;
    float *msg;
    int *deg, *rs, *cur, *edges;
    cudaGetSymbolAddress((void**)&hat_hi, g_hat_hi); cudaGetSymbolAddress((void**)&hat_lo, g_hat_lo);
    cudaGetSymbolAddress((void**)&hcl_hi, g_hcl_hi); cudaGetSymbolAddress((void**)&hcl_lo, g_hcl_lo);
    cudaGetSymbolAddress((void**)&hon_hi, g_hon_hi); cudaGetSymbolAddress((void**)&hon_lo, g_hon_lo);
    cudaGetSymbolAddress((void**)&uhi, g_uhi);  cudaGetSymbolAddress((void**)&ulo, g_ulo);
    cudaGetSymbolAddress((void**)&thi, g_thi);  cudaGetSymbolAddress((void**)&tlo, g_tlo);
    cudaGetSymbolAddress((void**)&whi, g_whi);  cudaGetSymbolAddress((void**)&wlo, g_wlo);
    cudaGetSymbolAddress((void**)&msg, g_msg);
    cudaGetSymbolAddress((void**)&deg, g_deg);
    cudaGetSymbolAddress((void**)&rs, g_rs);
    cudaGetSymbolAddress((void**)&cur, g_cur);
    cudaGetSymbolAddress((void**)&edges, g_edges);

    const size_t O_AT_IN = 0, O_AT_OUT = 65536, O_CL_IN = 131072, O_CL_OUT = 147456,
                 O_ON_IN = 163840, O_ON_OUT = 229376, O_U_IN = 294912, O_U_OUT = 360448;

    convW_all<<<(393216 + 255) / 256, 256>>>(w_in[0], w_out[0], w_in[1], w_out[1],
                                             w_in[2], w_out[2], wui, wuo, whi, wlo);

    // ---- CSR build (once) ----
    cudaMemsetAsync(deg, 0, NN * sizeof(int));
    cudaMemsetAsync(cur, 0, NN * sizeof(int));
    count_deg<<<(TROWS + 255) / 256, 256>>>(at, cl, on, deg);
    scan_deg<<<1, 1024>>>(deg, rs);
    scatter_edges<<<(TROWS + 255) / 256, 256>>>(at, cl, on, rs, cur, edges);

    const int SMEM = 2 * STAGE_BYTES;   // 61440
    cudaFuncSetAttribute(gemm_hmma<0, true>,  cudaFuncAttributeMaxDynamicSharedMemorySize, SMEM);
    cudaFuncSetAttribute(gemm_hmma<1, false>, cudaFuncAttributeMaxDynamicSharedMemorySize, SMEM);
    cudaFuncSetAttribute(gemm_hmma<0, false>, cudaFuncAttributeMaxDynamicSharedMemorySize, SMEM);
    cudaFuncSetAttribute(gemm_hmma<2, false>, cudaFuncAttributeMaxDynamicSharedMemorySize, SMEM);

    cudaMemcpyAsync(h, emb, (size_t)NN * 128 * sizeof(float), cudaMemcpyDeviceToDevice);

    // ---- batch argument blocks ----
    BatchArgs gin = {};   // relation in-GEMMs (MODE 0, gather-A from h)
    BatchArgs gout = {};  // relation out-GEMMs (MODE 1, residual gathered from h)
    BatchArgs gu0 = {};   // update hidden GEMM (MODE 0)
    BatchArgs gu1 = {};   // update out GEMM (MODE 2)

    unsigned short* hh_[3] = { hat_hi, hcl_hi, hon_hi };
    unsigned short* hl_[3] = { hat_lo, hcl_lo, hon_lo };
    const size_t wIn[3]  = { O_AT_IN, O_CL_IN, O_ON_IN };
    const size_t wOut[3] = { O_AT_OUT, O_CL_OUT, O_ON_OUT };
    const int nz[3] = { 256, 128, 256 };
    const size_t msgOff[3] = { 0, (size_t)300000 * 128, (size_t)450000 * 128 };
    const int* atoms[3] = { at, cl, on };

    for (int zz = 0; zz < 3; zz++) {
        gin.Bhi[zz] = whi + wIn[zz]; gin.Blo[zz] = wlo + wIn[zz];
        gin.bias[zz] = b_in[zz];
        gin.Chi[zz] = hh_[zz]; gin.Clo[zz] = hl_[zz];
        gin.idx[zz] = atoms[zz];
        gin.N[zz] = nz[zz]; gin.K[zz] = nz[zz];

        gout.Ahi[zz] = hh_[zz]; gout.Alo[zz] = hl_[zz];
        gout.Bhi[zz] = whi + wOut[zz]; gout.Blo[zz] = wlo + wOut[zz];
        gout.bias[zz] = b_out[zz];
        gout.Cf[zz] = msg + msgOff[zz];
        gout.idx[zz] = atoms[zz];
        gout.N[zz] = nz[zz]; gout.K[zz] = nz[zz];
    }
    gu0.Ahi[0] = uhi; gu0.Alo[0] = ulo;
    gu0.Bhi[0] = whi + O_U_IN; gu0.Blo[0] = wlo + O_U_IN;
    gu0.bias[0] = bui; gu0.Chi[0] = thi; gu0.Clo[0] = tlo;
    gu0.N[0] = 256; gu0.K[0] = 256;

    gu1.Ahi[0] = thi; gu1.Alo[0] = tlo;
    gu1.Bhi[0] = whi + O_U_OUT; gu1.Blo[0] = wlo + O_U_OUT;
    gu1.bias[0] = buo; gu1.Xf[0] = h; gu1.Cf[0] = h;
    gu1.N[0] = 128; gu1.K[0] = 256;

    const dim3 gRel(2, MPAD_A / 64, 3);
    const dim3 gUp0(2, MPAD_N / 64, 1);
    const dim3 gUp1(1, MPAD_N / 64, 1);

    for (int layer = 0; layer < 4; layer++) {
        gemm_hmma<0, true><<<gRel, 256, SMEM>>>(gin, h, A_AT);
        gemm_hmma<1, false><<<gRel, 256, SMEM>>>(gout, h, A_AT);

        aggregate_updin<<<(NN + 3) / 4, 128>>>(msg, rs, edges, h, uhi, ulo);

        gemm_hmma<0, false><<<gUp0, 256, SMEM>>>(gu0, nullptr, NN);
        gemm_hmma<2, false><<<gUp1, 256, SMEM>>>(gu1, nullptr, NN);
    }
}